// round 13
// baseline (speedup 1.0000x reference)
#include <cuda_runtime.h>
#include <cstdint>

#define QN 16
#define DD 384
#define NCOL 1000000
#define TPB 256
#define NWARP 8
#define CPB 512                                   // cols per block
#define WCOLS 64                                  // cols per warp
#define NBLK ((NCOL + CPB - 1) / CPB)             // 1954
#define NK (DD / 8)                               // 48 k-groups
#define NSTAGE 4
#define SB_STRIDE 72                              // 64 + 8 pad (conflict-free)
#define SB_TILE (8 * SB_STRIDE)                   // one stage, one warp: 576 f
#define NT 8                                      // n-tiles per warp (64 cols)

#define NPART 4                                   // pass-2 blocks per query
#define CTOP 4                                    // candidates per part
#define LK 2                                      // per-thread survivors

#define QF_FLOATS (NK * 32 * 4)                   // 6144 floats = 24.5 KB
#define SB_WARP (NSTAGE * SB_TILE)                // 2304 floats per warp
#define SB_FLOATS (NWARP * SB_WARP)               // 18432 floats = 73.7 KB
#define SMEM_BYTES (QF_FLOATS * 4 + SB_FLOATS * 4 + NWARP * 16 * 16)

__device__ __forceinline__ float neg_inf() { return __int_as_float(0xff800000); }

struct __align__(16) Top2 {
    float v1;
    float v2;
    int   i1;
    int   i2;
};

struct __align__(8) Cand {
    float v;
    int   i;
};

// transposed: g_part[qi * NBLK + blk]
__device__ Top2 g_part[QN * NBLK];
__device__ Cand g_cand[QN * NPART * CTOP];

__device__ __forceinline__ bool before(float va, int ia, float vb, int ib) {
    return (va > vb) || (va == vb && ia < ib);
}

__device__ __forceinline__ void merge_one(float& v1, int& i1, float& v2, int& i2,
                                          float s, int idx) {
    if (before(s, idx, v1, i1)) {
        v2 = v1; i2 = i1; v1 = s; i1 = idx;
    } else if (before(s, idx, v2, i2)) {
        v2 = s; i2 = idx;
    }
}

__device__ __forceinline__ void merge_pair(float& v1, int& i1, float& v2, int& i2,
                                           float w1, int j1, float w2, int j2) {
    merge_one(v1, i1, v2, i2, w1, j1);
    merge_one(v1, i1, v2, i2, w2, j2);
}

__device__ __forceinline__ void mma_tf32(float* c, const uint32_t* a,
                                         uint32_t b0, uint32_t b1) {
    asm volatile(
        "mma.sync.aligned.m16n8k8.row.col.f32.tf32.tf32.f32 "
        "{%0,%1,%2,%3}, {%4,%5,%6,%7}, {%8,%9}, {%0,%1,%2,%3};"
        : "+f"(c[0]), "+f"(c[1]), "+f"(c[2]), "+f"(c[3])
        : "r"(a[0]), "r"(a[1]), "r"(a[2]), "r"(a[3]), "r"(b0), "r"(b1));
}

__device__ __forceinline__ void cp16(uint32_t dst, const float* src) {
    asm volatile("cp.async.cg.shared.global [%0], [%1], 16;" :: "r"(dst), "l"(src));
}

// ---------------------------------------------------------------------------
// Pass 1: single-tf32 approximate scoring. CPB=512 for 2KB-contiguous DRAM
// clusters per bank row. Warp-private cp.async pipelines, warp owns 64 cols.
// ---------------------------------------------------------------------------
__global__ __launch_bounds__(TPB, 2) void sim_kernel(const float* __restrict__ q,
                                                     const float* __restrict__ bank,
                                                     const int* __restrict__ startp,
                                                     const int* __restrict__ endp) {
    extern __shared__ __align__(16) float smem[];
    float4* qf = reinterpret_cast<float4*>(smem);    // [NK][32] float4
    float* sB = smem + QF_FLOATS;                    // [NWARP][NSTAGE][8][72]
    Top2* sred = reinterpret_cast<Top2*>(smem + QF_FLOATS + SB_FLOATS);

    const int start = startp ? *startp : 400000;
    const int end   = endp   ? *endp   : 450000;
    const int cb = blockIdx.x * CPB;
    const int tid = threadIdx.x;
    const int wid = tid >> 5;
    const int lane = tid & 31;

    // Whole block inside exclusion window -> emit sentinels and exit.
    if (cb >= start && cb + CPB <= end) {
        if (tid < QN) {
            Top2 t;
            t.v1 = neg_inf(); t.v2 = neg_inf();
            t.i1 = 0x7fffffff; t.i2 = 0x7fffffff;
            g_part[tid * NBLK + blockIdx.x] = t;
        }
        return;
    }

    // per-warp staging coordinates: lane loads 16 floats (4 x 16B) of one row
    const int srow = lane >> 2;                // 0..7 (k row within stage)
    const int scol = (lane & 3) * 16;          // 0,16,32,48
    int gc = cb + wid * WCOLS + scol;
    if (gc > NCOL - 16) gc = NCOL - 16;        // clamp (garbage masked later)
    const float* gsrc = bank + (size_t)srow * NCOL + gc;
    float* wB = sB + wid * SB_WARP;
    uint32_t sbase = (uint32_t)__cvta_generic_to_shared(wB) +
                     (srow * SB_STRIDE + scol) * 4;

    // prologue: stages 0..NSTAGE-2 (issue BEFORE the A-fragment preamble)
    #pragma unroll
    for (int s = 0; s < NSTAGE - 1; ++s) {
        const float* src = gsrc + (size_t)(s * 8) * NCOL;
        uint32_t dst = sbase + s * (SB_TILE * 4);
        cp16(dst, src);
        cp16(dst + 16, src + 4);
        cp16(dst + 32, src + 8);
        cp16(dst + 48, src + 12);
        asm volatile("cp.async.commit_group;" ::: "memory");
    }

    // --- build pre-swizzled A fragments: qf[kg][gp*4+tk] =
    //     {q[gp][8kg+tk], q[gp+8][8kg+tk], q[gp][8kg+4+tk], q[gp+8][8kg+4+tk]}
    for (int w = tid; w < NK * 8; w += TPB) {
        const int kg = w >> 3;
        const int gp = w & 7;
        const float4* qa = reinterpret_cast<const float4*>(q + gp * DD + kg * 8);
        const float4* qb = reinterpret_cast<const float4*>(q + (gp + 8) * DD + kg * 8);
        float4 alo = qa[0], ahi = qa[1];
        float4 blo = qb[0], bhi = qb[1];
        float4* dst = qf + kg * 32 + gp * 4;
        dst[0] = make_float4(alo.x, blo.x, ahi.x, bhi.x);
        dst[1] = make_float4(alo.y, blo.y, ahi.y, bhi.y);
        dst[2] = make_float4(alo.z, blo.z, ahi.z, bhi.z);
        dst[3] = make_float4(alo.w, blo.w, ahi.w, bhi.w);
    }
    __syncthreads();   // qf visible to all warps (only block barrier)

    const int tk = lane & 3;                   // thread-in-group (k index)
    const int g  = lane >> 2;                  // group id (row / n index)

    float c[NT][4];
    #pragma unroll
    for (int nt = 0; nt < NT; ++nt)
        #pragma unroll
        for (int i = 0; i < 4; ++i) c[nt][i] = 0.f;

    for (int kg = 0; kg < NK; ++kg) {
        // issue stage kg+NSTAGE-1 (buffer consumed at kg-1; warp-private)
        if (kg + NSTAGE - 1 < NK) {
            const float* src = gsrc + (size_t)((kg + NSTAGE - 1) * 8) * NCOL;
            uint32_t dst = sbase +
                (uint32_t)((kg + NSTAGE - 1) & (NSTAGE - 1)) * (SB_TILE * 4);
            cp16(dst, src);
            cp16(dst + 16, src + 4);
            cp16(dst + 32, src + 8);
            cp16(dst + 48, src + 12);
        }
        asm volatile("cp.async.commit_group;" ::: "memory");
        asm volatile("cp.async.wait_group 3;" ::: "memory");   // stage kg ready
        __syncwarp();

        // A fragment: one LDS.128 (raw bits; HW truncates to tf32)
        float4 af = qf[kg * 32 + lane];
        uint32_t ah[4] = {__float_as_uint(af.x), __float_as_uint(af.y),
                          __float_as_uint(af.z), __float_as_uint(af.w)};

        const float* sb = wB + (kg & (NSTAGE - 1)) * SB_TILE;
        #pragma unroll
        for (int nt = 0; nt < NT; ++nt) {
            const int cB = nt * 8 + g;
            uint32_t b0 = __float_as_uint(sb[tk * SB_STRIDE + cB]);
            uint32_t b1 = __float_as_uint(sb[(tk + 4) * SB_STRIDE + cB]);
            mma_tf32(c[nt], ah, b0, b1);
        }
    }

    // --- epilogue: per-thread top2 for rows g and g+8, quad reduce ---
    float v1l = neg_inf(), v2l = neg_inf();
    int i1l = 0x7fffffff, i2l = 0x7fffffff;
    float v1h = neg_inf(), v2h = neg_inf();
    int i1h = 0x7fffffff, i2h = 0x7fffffff;

    #pragma unroll
    for (int nt = 0; nt < NT; ++nt) {
        const int col0 = cb + wid * WCOLS + nt * 8 + 2 * tk;
        const int col1 = col0 + 1;
        const bool ok0 = (col0 < NCOL) && !(col0 >= start && col0 < end);
        const bool ok1 = (col1 < NCOL) && !(col1 >= start && col1 < end);
        if (ok0) {
            merge_one(v1l, i1l, v2l, i2l, c[nt][0], col0);
            merge_one(v1h, i1h, v2h, i2h, c[nt][2], col0);
        }
        if (ok1) {
            merge_one(v1l, i1l, v2l, i2l, c[nt][1], col1);
            merge_one(v1h, i1h, v2h, i2h, c[nt][3], col1);
        }
    }
    #pragma unroll
    for (int off = 1; off <= 2; off <<= 1) {
        float w1, w2; int j1, j2;
        w1 = __shfl_xor_sync(0xffffffffu, v1l, off);
        j1 = __shfl_xor_sync(0xffffffffu, i1l, off);
        w2 = __shfl_xor_sync(0xffffffffu, v2l, off);
        j2 = __shfl_xor_sync(0xffffffffu, i2l, off);
        merge_pair(v1l, i1l, v2l, i2l, w1, j1, w2, j2);
        w1 = __shfl_xor_sync(0xffffffffu, v1h, off);
        j1 = __shfl_xor_sync(0xffffffffu, i1h, off);
        w2 = __shfl_xor_sync(0xffffffffu, v2h, off);
        j2 = __shfl_xor_sync(0xffffffffu, i2h, off);
        merge_pair(v1h, i1h, v2h, i2h, w1, j1, w2, j2);
    }
    if (tk == 0) {
        Top2 tl; tl.v1 = v1l; tl.v2 = v2l; tl.i1 = i1l; tl.i2 = i2l;
        sred[wid * 16 + g] = tl;
        Top2 th; th.v1 = v1h; th.v2 = v2h; th.i1 = i1h; th.i2 = i2h;
        sred[wid * 16 + 8 + g] = th;
    }
    __syncthreads();

    if (tid < QN) {
        float v1 = neg_inf(), v2 = neg_inf();
        int i1 = 0x7fffffff, i2 = 0x7fffffff;
        #pragma unroll
        for (int w = 0; w < NWARP; ++w) {
            Top2 t = sred[w * 16 + tid];
            merge_pair(v1, i1, v2, i2, t.v1, t.i1, t.v2, t.i2);
        }
        Top2 r; r.v1 = v1; r.v2 = v2; r.i1 = i1; r.i2 = i2;
        g_part[tid * NBLK + blockIdx.x] = r;
    }
}

// ---------------------------------------------------------------------------
// Pass 2a: (query, part) blocks. Scan 1/NPART of the partials, per-thread
// top-2, extract top-4 survivors, exact fp32 rescore, write to g_cand.
// ---------------------------------------------------------------------------
__global__ __launch_bounds__(TPB) void cand_kernel(const float* __restrict__ q,
                                                   const float* __restrict__ bank,
                                                   int nblocks) {
    __shared__ float sv[TPB * LK];
    __shared__ int   sc[TPB * LK];
    __shared__ float qn[DD];
    __shared__ float redv[8];
    __shared__ int   redc[8];
    __shared__ int   redp[8];
    __shared__ float candv[CTOP];
    __shared__ int   candc[CTOP];

    const int qi = blockIdx.x;
    const int part = blockIdx.y;
    const int tid = threadIdx.x;
    const int lane = tid & 31;
    const int warp = tid >> 5;

    const int chunk = (nblocks + NPART - 1) / NPART;
    const int b0 = part * chunk;
    const int b1 = min(nblocks, b0 + chunk);

    // --- per-thread top-2 over coalesced partial slice ---
    float lv[LK];
    int   lc[LK];
    #pragma unroll
    for (int i = 0; i < LK; ++i) { lv[i] = neg_inf(); lc[i] = 0x7fffffff; }

    const Top2* gp = g_part + (size_t)qi * nblocks;
    for (int b = b0 + tid; b < b1; b += TPB) {
        Top2 t = gp[b];
        #pragma unroll
        for (int h = 0; h < 2; ++h) {
            float x = h ? t.v2 : t.v1;
            int  xi = h ? t.i2 : t.i1;
            if (before(x, xi, lv[1], lc[1])) {
                if (before(x, xi, lv[0], lc[0])) {
                    lv[1] = lv[0]; lc[1] = lc[0];
                    lv[0] = x; lc[0] = xi;
                } else { lv[1] = x; lc[1] = xi; }
            }
        }
    }
    #pragma unroll
    for (int i = 0; i < LK; ++i) {
        sv[tid + i * TPB] = lv[i];
        sc[tid + i * TPB] = lc[i];
    }

    // --- normalized query into qn ---
    float s = 0.f;
    for (int d = tid; d < DD; d += TPB) s += fabsf(q[qi * DD + d]);
    #pragma unroll
    for (int o = 16; o; o >>= 1) s += __shfl_xor_sync(0xffffffffu, s, o);
    if (lane == 0) redv[warp] = s;
    __syncthreads();
    if (tid == 0) {
        float tot = 0.f;
        #pragma unroll
        for (int w = 0; w < 8; ++w) tot += redv[w];
        redv[0] = 1.0f / fmaxf(tot, 1e-12f);
    }
    __syncthreads();
    const float inv = redv[0];
    for (int d = tid; d < DD; d += TPB) qn[d] = q[qi * DD + d] * inv;
    __syncthreads();

    // --- extract top-4 from the 512 survivors ---
    for (int it = 0; it < CTOP; ++it) {
        float bv = neg_inf(); int bc = 0x7fffffff; int bp = -1;
        #pragma unroll
        for (int k = 0; k < LK; ++k) {
            int e = tid + k * TPB;
            float v = sv[e];
            int cc = sc[e];
            if (before(v, cc, bv, bc)) { bv = v; bc = cc; bp = e; }
        }
        #pragma unroll
        for (int o = 16; o; o >>= 1) {
            float wv = __shfl_xor_sync(0xffffffffu, bv, o);
            int wc = __shfl_xor_sync(0xffffffffu, bc, o);
            int wp = __shfl_xor_sync(0xffffffffu, bp, o);
            if (before(wv, wc, bv, bc)) { bv = wv; bc = wc; bp = wp; }
        }
        if (lane == 0) { redv[warp] = bv; redc[warp] = bc; redp[warp] = bp; }
        __syncthreads();
        if (tid == 0) {
            float fv = redv[0]; int fc = redc[0], fp = redp[0];
            #pragma unroll
            for (int w = 1; w < 8; ++w)
                if (before(redv[w], redc[w], fv, fc)) {
                    fv = redv[w]; fc = redc[w]; fp = redp[w];
                }
            candv[it] = fv; candc[it] = fc;
            if (fp >= 0) { sv[fp] = neg_inf(); sc[fp] = 0x7fffffff; }
        }
        __syncthreads();
    }

    // --- exact fp32 rescore of the 4 candidates (one warp per candidate) ---
    if (warp < CTOP) {
        const int col = candc[warp];
        float sum;
        if (col >= 0 && col < NCOL) {
            sum = 0.f;
            #pragma unroll
            for (int d = lane; d < DD; d += 32)
                sum += qn[d] * bank[(size_t)d * NCOL + col];
        } else {
            sum = neg_inf();
        }
        #pragma unroll
        for (int o = 16; o; o >>= 1) sum += __shfl_xor_sync(0xffffffffu, sum, o);
        if (lane == 0) {
            Cand cd; cd.v = sum; cd.i = col;
            g_cand[(qi * NPART + part) * CTOP + warp] = cd;
        }
    }
}

// ---------------------------------------------------------------------------
// Pass 2b: one warp per query merges the 16 exact candidates -> top-2 out.
// ---------------------------------------------------------------------------
__global__ void merge_kernel(float* __restrict__ out) {
    const int tid = threadIdx.x;
    const int qi = tid >> 5;
    const int lane = tid & 31;
    if (qi >= QN) return;

    float v1 = neg_inf(), v2 = neg_inf();
    int i1 = 0x7fffffff, i2 = 0x7fffffff;
    if (lane < NPART * CTOP) {
        Cand cd = g_cand[qi * (NPART * CTOP) + lane];
        v1 = cd.v; i1 = cd.i;
    }
    #pragma unroll
    for (int o = 16; o; o >>= 1) {
        float w1 = __shfl_xor_sync(0xffffffffu, v1, o);
        int   j1 = __shfl_xor_sync(0xffffffffu, i1, o);
        float w2 = __shfl_xor_sync(0xffffffffu, v2, o);
        int   j2 = __shfl_xor_sync(0xffffffffu, i2, o);
        merge_pair(v1, i1, v2, i2, w1, j1, w2, j2);
    }
    if (lane == 0) {
        out[qi * 2 + 0] = v1;
        out[qi * 2 + 1] = v2;
        out[QN * 2 + qi * 2 + 0] = (float)i1;
        out[QN * 2 + qi * 2 + 1] = (float)i2;
    }
}

extern "C" void kernel_launch(void* const* d_in, const int* in_sizes, int n_in,
                              void* d_out, int out_size) {
    const float* q    = (const float*)d_in[0];
    const float* bank = (const float*)d_in[1];
    const int* startp = (n_in > 2) ? (const int*)d_in[2] : nullptr;
    const int* endp   = (n_in > 3) ? (const int*)d_in[3] : nullptr;
    float* out = (float*)d_out;

    static int smem_set = 0;
    if (!smem_set) {
        cudaFuncSetAttribute(sim_kernel,
                             cudaFuncAttributeMaxDynamicSharedMemorySize,
                             SMEM_BYTES);
        smem_set = 1;
    }

    sim_kernel<<<NBLK, TPB, SMEM_BYTES>>>(q, bank, startp, endp);
    dim3 cgrid(QN, NPART);
    cand_kernel<<<cgrid, TPB>>>(q, bank, NBLK);
    merge_kernel<<<1, QN * 32>>>(out);
}

// round 14
// speedup vs baseline: 1.1543x; 1.1543x over previous
#include <cuda_runtime.h>
#include <cstdint>

#define QN 16
#define DD 384
#define NCOL 1000000
#define TPB 256
#define NWARP 8
#define CPB 256                                   // cols per block
#define WCOLS 32                                  // cols per warp
#define NBLK ((NCOL + CPB - 1) / CPB)             // 3907
#define NK (DD / 8)                               // 48 k-groups
#define NSTAGE 4
#define SB_STRIDE 40                              // 32 + 8 pad (conflict-free)
#define SB_TILE (8 * SB_STRIDE)                   // one stage, one warp: 320 f
#define NT 4                                      // n-tiles per warp (32 cols)

#define NPART 4                                   // pass-2 blocks per query
#define CTOP 4                                    // candidates per part
#define LK 2                                      // per-thread survivors

#define QF_FLOATS (NK * 32 * 4)                   // 6144 floats = 24.5 KB
#define SB_WARP (NSTAGE * SB_TILE)                // 1280 floats per warp
#define SB_FLOATS (NWARP * SB_WARP)               // 10240 floats = 41 KB
#define SMEM_BYTES (QF_FLOATS * 4 + SB_FLOATS * 4 + NWARP * 16 * 16)

__device__ __forceinline__ float neg_inf() { return __int_as_float(0xff800000); }

struct __align__(16) Top2 {
    float v1;
    float v2;
    int   i1;
    int   i2;
};

struct __align__(8) Cand {
    float v;
    int   i;
};

// transposed: g_part[qi * NBLK + blk]
__device__ Top2 g_part[QN * NBLK];
__device__ Cand g_cand[QN * NPART * CTOP];
__device__ unsigned int g_ctr;   // zero-initialized; reset by merge block

__device__ __forceinline__ bool before(float va, int ia, float vb, int ib) {
    return (va > vb) || (va == vb && ia < ib);
}

__device__ __forceinline__ void merge_one(float& v1, int& i1, float& v2, int& i2,
                                          float s, int idx) {
    if (before(s, idx, v1, i1)) {
        v2 = v1; i2 = i1; v1 = s; i1 = idx;
    } else if (before(s, idx, v2, i2)) {
        v2 = s; i2 = idx;
    }
}

__device__ __forceinline__ void merge_pair(float& v1, int& i1, float& v2, int& i2,
                                           float w1, int j1, float w2, int j2) {
    merge_one(v1, i1, v2, i2, w1, j1);
    merge_one(v1, i1, v2, i2, w2, j2);
}

__device__ __forceinline__ void mma_tf32(float* c, const uint32_t* a,
                                         uint32_t b0, uint32_t b1) {
    asm volatile(
        "mma.sync.aligned.m16n8k8.row.col.f32.tf32.tf32.f32 "
        "{%0,%1,%2,%3}, {%4,%5,%6,%7}, {%8,%9}, {%0,%1,%2,%3};"
        : "+f"(c[0]), "+f"(c[1]), "+f"(c[2]), "+f"(c[3])
        : "r"(a[0]), "r"(a[1]), "r"(a[2]), "r"(a[3]), "r"(b0), "r"(b1));
}

__device__ __forceinline__ void cp16(uint32_t dst, const float* src) {
    asm volatile("cp.async.cg.shared.global [%0], [%1], 16;" :: "r"(dst), "l"(src));
}

// ---------------------------------------------------------------------------
// Pass 1: single-tf32 approximate scoring (ranking only; scale/error tolerant).
// A fragments pre-swizzled to one LDS.128 per kg. 3 blocks/SM (24 warps).
// ---------------------------------------------------------------------------
__global__ __launch_bounds__(TPB, 3) void sim_kernel(const float* __restrict__ q,
                                                     const float* __restrict__ bank,
                                                     const int* __restrict__ startp,
                                                     const int* __restrict__ endp) {
    extern __shared__ __align__(16) float smem[];
    float4* qf = reinterpret_cast<float4*>(smem);    // [NK][32] float4
    float* sB = smem + QF_FLOATS;                    // [NWARP][NSTAGE][8][40]
    Top2* sred = reinterpret_cast<Top2*>(smem + QF_FLOATS + SB_FLOATS);

    const int start = startp ? *startp : 400000;
    const int end   = endp   ? *endp   : 450000;
    const int cb = blockIdx.x * CPB;
    const int tid = threadIdx.x;
    const int wid = tid >> 5;
    const int lane = tid & 31;

    // Whole block inside exclusion window -> emit sentinels and exit.
    if (cb >= start && cb + CPB <= end) {
        if (tid < QN) {
            Top2 t;
            t.v1 = neg_inf(); t.v2 = neg_inf();
            t.i1 = 0x7fffffff; t.i2 = 0x7fffffff;
            g_part[tid * NBLK + blockIdx.x] = t;
        }
        return;
    }

    // per-warp staging coordinates: lane loads 8 floats of one row
    const int srow = lane >> 2;                // 0..7 (k row within stage)
    const int scol = (lane & 3) * 8;           // 0,8,16,24
    int gc = cb + wid * WCOLS + scol;
    if (gc > NCOL - 8) gc = NCOL - 8;          // clamp (garbage masked later)
    const float* gsrc = bank + (size_t)srow * NCOL + gc;
    float* wB = sB + wid * SB_WARP;
    uint32_t sbase = (uint32_t)__cvta_generic_to_shared(wB) +
                     (srow * SB_STRIDE + scol) * 4;

    // prologue: stages 0..NSTAGE-2 (issue BEFORE the A-fragment preamble so
    // the DRAM pipe starts immediately)
    #pragma unroll
    for (int s = 0; s < NSTAGE - 1; ++s) {
        const float* src = gsrc + (size_t)(s * 8) * NCOL;
        uint32_t dst = sbase + s * (SB_TILE * 4);
        cp16(dst, src);
        cp16(dst + 16, src + 4);
        asm volatile("cp.async.commit_group;" ::: "memory");
    }

    // --- build pre-swizzled A fragments: qf[kg][gp*4+tk] =
    //     {q[gp][8kg+tk], q[gp+8][8kg+tk], q[gp][8kg+4+tk], q[gp+8][8kg+4+tk]}
    for (int w = tid; w < NK * 8; w += TPB) {
        const int kg = w >> 3;
        const int gp = w & 7;
        const float4* qa = reinterpret_cast<const float4*>(q + gp * DD + kg * 8);
        const float4* qb = reinterpret_cast<const float4*>(q + (gp + 8) * DD + kg * 8);
        float4 alo = qa[0], ahi = qa[1];
        float4 blo = qb[0], bhi = qb[1];
        float4* dst = qf + kg * 32 + gp * 4;
        dst[0] = make_float4(alo.x, blo.x, ahi.x, bhi.x);
        dst[1] = make_float4(alo.y, blo.y, ahi.y, bhi.y);
        dst[2] = make_float4(alo.z, blo.z, ahi.z, bhi.z);
        dst[3] = make_float4(alo.w, blo.w, ahi.w, bhi.w);
    }
    __syncthreads();   // qf visible to all warps (only block barrier)

    const int tk = lane & 3;                   // thread-in-group (k index)
    const int g  = lane >> 2;                  // group id (row / n index)

    float c[NT][4];
    #pragma unroll
    for (int nt = 0; nt < NT; ++nt)
        #pragma unroll
        for (int i = 0; i < 4; ++i) c[nt][i] = 0.f;

    for (int kg = 0; kg < NK; ++kg) {
        // issue stage kg+NSTAGE-1 (buffer consumed at kg-1; warp-private)
        if (kg + NSTAGE - 1 < NK) {
            const float* src = gsrc + (size_t)((kg + NSTAGE - 1) * 8) * NCOL;
            uint32_t dst = sbase +
                (uint32_t)((kg + NSTAGE - 1) & (NSTAGE - 1)) * (SB_TILE * 4);
            cp16(dst, src);
            cp16(dst + 16, src + 4);
        }
        asm volatile("cp.async.commit_group;" ::: "memory");
        asm volatile("cp.async.wait_group 3;" ::: "memory");   // stage kg ready
        __syncwarp();

        // A fragment: one LDS.128 (raw bits; HW truncates to tf32)
        float4 af = qf[kg * 32 + lane];
        uint32_t ah[4] = {__float_as_uint(af.x), __float_as_uint(af.y),
                          __float_as_uint(af.z), __float_as_uint(af.w)};

        const float* sb = wB + (kg & (NSTAGE - 1)) * SB_TILE;
        #pragma unroll
        for (int nt = 0; nt < NT; ++nt) {
            const int cB = nt * 8 + g;
            uint32_t b0 = __float_as_uint(sb[tk * SB_STRIDE + cB]);
            uint32_t b1 = __float_as_uint(sb[(tk + 4) * SB_STRIDE + cB]);
            mma_tf32(c[nt], ah, b0, b1);
        }
    }

    // --- epilogue: per-thread top2 for rows g and g+8, quad reduce ---
    float v1l = neg_inf(), v2l = neg_inf();
    int i1l = 0x7fffffff, i2l = 0x7fffffff;
    float v1h = neg_inf(), v2h = neg_inf();
    int i1h = 0x7fffffff, i2h = 0x7fffffff;

    #pragma unroll
    for (int nt = 0; nt < NT; ++nt) {
        const int col0 = cb + wid * WCOLS + nt * 8 + 2 * tk;
        const int col1 = col0 + 1;
        const bool ok0 = (col0 < NCOL) && !(col0 >= start && col0 < end);
        const bool ok1 = (col1 < NCOL) && !(col1 >= start && col1 < end);
        if (ok0) {
            merge_one(v1l, i1l, v2l, i2l, c[nt][0], col0);
            merge_one(v1h, i1h, v2h, i2h, c[nt][2], col0);
        }
        if (ok1) {
            merge_one(v1l, i1l, v2l, i2l, c[nt][1], col1);
            merge_one(v1h, i1h, v2h, i2h, c[nt][3], col1);
        }
    }
    #pragma unroll
    for (int off = 1; off <= 2; off <<= 1) {
        float w1, w2; int j1, j2;
        w1 = __shfl_xor_sync(0xffffffffu, v1l, off);
        j1 = __shfl_xor_sync(0xffffffffu, i1l, off);
        w2 = __shfl_xor_sync(0xffffffffu, v2l, off);
        j2 = __shfl_xor_sync(0xffffffffu, i2l, off);
        merge_pair(v1l, i1l, v2l, i2l, w1, j1, w2, j2);
        w1 = __shfl_xor_sync(0xffffffffu, v1h, off);
        j1 = __shfl_xor_sync(0xffffffffu, i1h, off);
        w2 = __shfl_xor_sync(0xffffffffu, v2h, off);
        j2 = __shfl_xor_sync(0xffffffffu, i2h, off);
        merge_pair(v1h, i1h, v2h, i2h, w1, j1, w2, j2);
    }
    if (tk == 0) {
        Top2 tl; tl.v1 = v1l; tl.v2 = v2l; tl.i1 = i1l; tl.i2 = i2l;
        sred[wid * 16 + g] = tl;
        Top2 th; th.v1 = v1h; th.v2 = v2h; th.i1 = i1h; th.i2 = i2h;
        sred[wid * 16 + 8 + g] = th;
    }
    __syncthreads();

    if (tid < QN) {
        float v1 = neg_inf(), v2 = neg_inf();
        int i1 = 0x7fffffff, i2 = 0x7fffffff;
        #pragma unroll
        for (int w = 0; w < NWARP; ++w) {
            Top2 t = sred[w * 16 + tid];
            merge_pair(v1, i1, v2, i2, t.v1, t.i1, t.v2, t.i2);
        }
        Top2 r; r.v1 = v1; r.v2 = v2; r.i1 = i1; r.i2 = i2;
        g_part[tid * NBLK + blockIdx.x] = r;
    }
}

// ---------------------------------------------------------------------------
// Pass 2 (fused): (query, part) blocks select + exact-rescore 4 candidates;
// the LAST block to finish merges all 16x(NPART*CTOP) candidates -> out.
// ---------------------------------------------------------------------------
__global__ __launch_bounds__(TPB) void cand_kernel(float* __restrict__ out,
                                                   const float* __restrict__ q,
                                                   const float* __restrict__ bank,
                                                   int nblocks) {
    __shared__ float sv[TPB * LK];
    __shared__ int   sc[TPB * LK];
    __shared__ float qn[DD];
    __shared__ float redv[8];
    __shared__ int   redc[8];
    __shared__ int   redp[8];
    __shared__ float candv[CTOP];
    __shared__ int   candc[CTOP];
    __shared__ unsigned int s_last;

    const int qi = blockIdx.x;
    const int part = blockIdx.y;
    const int tid = threadIdx.x;
    const int lane = tid & 31;
    const int warp = tid >> 5;

    const int chunk = (nblocks + NPART - 1) / NPART;
    const int b0 = part * chunk;
    const int b1 = min(nblocks, b0 + chunk);

    // --- per-thread top-2 over coalesced partial slice ---
    float lv[LK];
    int   lc[LK];
    #pragma unroll
    for (int i = 0; i < LK; ++i) { lv[i] = neg_inf(); lc[i] = 0x7fffffff; }

    const Top2* gp = g_part + (size_t)qi * nblocks;
    for (int b = b0 + tid; b < b1; b += TPB) {
        Top2 t = gp[b];
        #pragma unroll
        for (int h = 0; h < 2; ++h) {
            float x = h ? t.v2 : t.v1;
            int  xi = h ? t.i2 : t.i1;
            if (before(x, xi, lv[1], lc[1])) {
                if (before(x, xi, lv[0], lc[0])) {
                    lv[1] = lv[0]; lc[1] = lc[0];
                    lv[0] = x; lc[0] = xi;
                } else { lv[1] = x; lc[1] = xi; }
            }
        }
    }
    #pragma unroll
    for (int i = 0; i < LK; ++i) {
        sv[tid + i * TPB] = lv[i];
        sc[tid + i * TPB] = lc[i];
    }

    // --- normalized query into qn ---
    float s = 0.f;
    for (int d = tid; d < DD; d += TPB) s += fabsf(q[qi * DD + d]);
    #pragma unroll
    for (int o = 16; o; o >>= 1) s += __shfl_xor_sync(0xffffffffu, s, o);
    if (lane == 0) redv[warp] = s;
    __syncthreads();
    if (tid == 0) {
        float tot = 0.f;
        #pragma unroll
        for (int w = 0; w < 8; ++w) tot += redv[w];
        redv[0] = 1.0f / fmaxf(tot, 1e-12f);
    }
    __syncthreads();
    const float inv = redv[0];
    for (int d = tid; d < DD; d += TPB) qn[d] = q[qi * DD + d] * inv;
    __syncthreads();

    // --- extract top-4 from the 512 survivors ---
    for (int it = 0; it < CTOP; ++it) {
        float bv = neg_inf(); int bc = 0x7fffffff; int bp = -1;
        #pragma unroll
        for (int k = 0; k < LK; ++k) {
            int e = tid + k * TPB;
            float v = sv[e];
            int cc = sc[e];
            if (before(v, cc, bv, bc)) { bv = v; bc = cc; bp = e; }
        }
        #pragma unroll
        for (int o = 16; o; o >>= 1) {
            float wv = __shfl_xor_sync(0xffffffffu, bv, o);
            int wc = __shfl_xor_sync(0xffffffffu, bc, o);
            int wp = __shfl_xor_sync(0xffffffffu, bp, o);
            if (before(wv, wc, bv, bc)) { bv = wv; bc = wc; bp = wp; }
        }
        if (lane == 0) { redv[warp] = bv; redc[warp] = bc; redp[warp] = bp; }
        __syncthreads();
        if (tid == 0) {
            float fv = redv[0]; int fc = redc[0], fp = redp[0];
            #pragma unroll
            for (int w = 1; w < 8; ++w)
                if (before(redv[w], redc[w], fv, fc)) {
                    fv = redv[w]; fc = redc[w]; fp = redp[w];
                }
            candv[it] = fv; candc[it] = fc;
            if (fp >= 0) { sv[fp] = neg_inf(); sc[fp] = 0x7fffffff; }
        }
        __syncthreads();
    }

    // --- exact fp32 rescore of the 4 candidates (one warp per candidate) ---
    if (warp < CTOP) {
        const int col = candc[warp];
        float sum;
        if (col >= 0 && col < NCOL) {
            sum = 0.f;
            #pragma unroll
            for (int d = lane; d < DD; d += 32)
                sum += qn[d] * bank[(size_t)d * NCOL + col];
        } else {
            sum = neg_inf();
        }
        #pragma unroll
        for (int o = 16; o; o >>= 1) sum += __shfl_xor_sync(0xffffffffu, sum, o);
        if (lane == 0) {
            Cand cd; cd.v = sum; cd.i = col;
            g_cand[(qi * NPART + part) * CTOP + warp] = cd;
        }
    }
    __syncthreads();

    // --- completion counter: last block merges everything ---
    if (tid == 0) {
        __threadfence();
        unsigned int prev = atomicAdd(&g_ctr, 1u);
        s_last = (prev == (unsigned int)(QN * NPART - 1)) ? 1u : 0u;
    }
    __syncthreads();
    if (s_last) {
        __threadfence();
        // warp w merges queries w and w+8 (8 warps, 16 queries)
        #pragma unroll
        for (int qq = warp; qq < QN; qq += 8) {
            float v1 = neg_inf(), v2 = neg_inf();
            int i1 = 0x7fffffff, i2 = 0x7fffffff;
            if (lane < NPART * CTOP) {
                Cand cd = g_cand[qq * (NPART * CTOP) + lane];
                v1 = cd.v; i1 = cd.i;
            }
            #pragma unroll
            for (int o = 16; o; o >>= 1) {
                float w1 = __shfl_xor_sync(0xffffffffu, v1, o);
                int   j1 = __shfl_xor_sync(0xffffffffu, i1, o);
                float w2 = __shfl_xor_sync(0xffffffffu, v2, o);
                int   j2 = __shfl_xor_sync(0xffffffffu, i2, o);
                merge_pair(v1, i1, v2, i2, w1, j1, w2, j2);
            }
            if (lane == 0) {
                out[qq * 2 + 0] = v1;
                out[qq * 2 + 1] = v2;
                out[QN * 2 + qq * 2 + 0] = (float)i1;
                out[QN * 2 + qq * 2 + 1] = (float)i2;
            }
        }
        __syncthreads();
        if (tid == 0) g_ctr = 0;   // reset for next graph replay
    }
}

extern "C" void kernel_launch(void* const* d_in, const int* in_sizes, int n_in,
                              void* d_out, int out_size) {
    const float* q    = (const float*)d_in[0];
    const float* bank = (const float*)d_in[1];
    const int* startp = (n_in > 2) ? (const int*)d_in[2] : nullptr;
    const int* endp   = (n_in > 3) ? (const int*)d_in[3] : nullptr;
    float* out = (float*)d_out;

    static int smem_set = 0;
    if (!smem_set) {
        cudaFuncSetAttribute(sim_kernel,
                             cudaFuncAttributeMaxDynamicSharedMemorySize,
                             SMEM_BYTES);
        smem_set = 1;
    }

    sim_kernel<<<NBLK, TPB, SMEM_BYTES>>>(q, bank, startp, endp);
    dim3 cgrid(QN, NPART);
    cand_kernel<<<cgrid, TPB>>>(out, q, bank, NBLK);
}

// round 15
// speedup vs baseline: 1.1583x; 1.0034x over previous
#include <cuda_runtime.h>
#include <cstdint>

#define QN 16
#define DD 384
#define NCOL 1000000
#define TPB 256
#define NWARP 8
#define CPB 256                                   // cols per block
#define WCOLS 32                                  // cols per warp
#define NBLK ((NCOL + CPB - 1) / CPB)             // 3907
#define NK (DD / 8)                               // 48 k-groups
#define NSTAGE 4
#define SB_STRIDE 40                              // 32 + 8 pad (conflict-free)
#define SB_TILE (8 * SB_STRIDE)                   // one stage, one warp: 320 f
#define NT 4                                      // n-tiles per warp (32 cols)

#define NPART 4                                   // pass-2 blocks per query
#define CTOP 4                                    // candidates per part
#define LK 2                                      // per-thread survivors

#define QF_FLOATS (NK * 32 * 4)                   // 6144 floats = 24.5 KB
#define SB_WARP (NSTAGE * SB_TILE)                // 1280 floats per warp
#define SB_FLOATS (NWARP * SB_WARP)               // 10240 floats = 41 KB
#define SMEM_BYTES (QF_FLOATS * 4 + SB_FLOATS * 4 + NWARP * 16 * 16)

__device__ __forceinline__ float neg_inf() { return __int_as_float(0xff800000); }

struct __align__(16) Top2 {
    float v1;
    float v2;
    int   i1;
    int   i2;
};

struct __align__(8) Cand {
    float v;
    int   i;
};

// transposed: g_part[qi * NBLK + blk]
__device__ Top2 g_part[QN * NBLK];
__device__ Cand g_cand[QN * NPART * CTOP];
__device__ unsigned int g_ctr;   // zero-initialized; reset by merge block

__device__ __forceinline__ bool before(float va, int ia, float vb, int ib) {
    return (va > vb) || (va == vb && ia < ib);
}

__device__ __forceinline__ void merge_one(float& v1, int& i1, float& v2, int& i2,
                                          float s, int idx) {
    if (before(s, idx, v1, i1)) {
        v2 = v1; i2 = i1; v1 = s; i1 = idx;
    } else if (before(s, idx, v2, i2)) {
        v2 = s; i2 = idx;
    }
}

__device__ __forceinline__ void merge_pair(float& v1, int& i1, float& v2, int& i2,
                                           float w1, int j1, float w2, int j2) {
    merge_one(v1, i1, v2, i2, w1, j1);
    merge_one(v1, i1, v2, i2, w2, j2);
}

__device__ __forceinline__ void mma_tf32(float* c, const uint32_t* a,
                                         uint32_t b0, uint32_t b1) {
    asm volatile(
        "mma.sync.aligned.m16n8k8.row.col.f32.tf32.tf32.f32 "
        "{%0,%1,%2,%3}, {%4,%5,%6,%7}, {%8,%9}, {%0,%1,%2,%3};"
        : "+f"(c[0]), "+f"(c[1]), "+f"(c[2]), "+f"(c[3])
        : "r"(a[0]), "r"(a[1]), "r"(a[2]), "r"(a[3]), "r"(b0), "r"(b1));
}

__device__ __forceinline__ void cp16(uint32_t dst, const float* src) {
    asm volatile("cp.async.cg.shared.global [%0], [%1], 16;" :: "r"(dst), "l"(src));
}

// ---------------------------------------------------------------------------
// Pass 1: single-tf32 approximate scoring (ranking only; scale/error tolerant).
// A fragments pre-swizzled to one LDS.128 per kg. 3 blocks/SM (24 warps).
// ---------------------------------------------------------------------------
__global__ __launch_bounds__(TPB, 3) void sim_kernel(const float* __restrict__ q,
                                                     const float* __restrict__ bank,
                                                     const int* __restrict__ startp,
                                                     const int* __restrict__ endp) {
    extern __shared__ __align__(16) float smem[];
    float4* qf = reinterpret_cast<float4*>(smem);    // [NK][32] float4
    float* sB = smem + QF_FLOATS;                    // [NWARP][NSTAGE][8][40]
    Top2* sred = reinterpret_cast<Top2*>(smem + QF_FLOATS + SB_FLOATS);

    const int start = startp ? *startp : 400000;
    const int end   = endp   ? *endp   : 450000;
    const int cb = blockIdx.x * CPB;
    const int tid = threadIdx.x;
    const int wid = tid >> 5;
    const int lane = tid & 31;

    // Whole block inside exclusion window -> emit sentinels and exit.
    if (cb >= start && cb + CPB <= end) {
        if (tid < QN) {
            Top2 t;
            t.v1 = neg_inf(); t.v2 = neg_inf();
            t.i1 = 0x7fffffff; t.i2 = 0x7fffffff;
            g_part[tid * NBLK + blockIdx.x] = t;
        }
        cudaTriggerProgrammaticLaunchCompletion();
        return;
    }

    // per-warp staging coordinates: lane loads 8 floats of one row
    const int srow = lane >> 2;                // 0..7 (k row within stage)
    const int scol = (lane & 3) * 8;           // 0,8,16,24
    int gc = cb + wid * WCOLS + scol;
    if (gc > NCOL - 8) gc = NCOL - 8;          // clamp (garbage masked later)
    const float* gsrc = bank + (size_t)srow * NCOL + gc;
    float* wB = sB + wid * SB_WARP;
    uint32_t sbase = (uint32_t)__cvta_generic_to_shared(wB) +
                     (srow * SB_STRIDE + scol) * 4;

    // prologue: stages 0..NSTAGE-2 (issue BEFORE the A-fragment preamble so
    // the DRAM pipe starts immediately)
    #pragma unroll
    for (int s = 0; s < NSTAGE - 1; ++s) {
        const float* src = gsrc + (size_t)(s * 8) * NCOL;
        uint32_t dst = sbase + s * (SB_TILE * 4);
        cp16(dst, src);
        cp16(dst + 16, src + 4);
        asm volatile("cp.async.commit_group;" ::: "memory");
    }

    // --- build pre-swizzled A fragments: qf[kg][gp*4+tk] =
    //     {q[gp][8kg+tk], q[gp+8][8kg+tk], q[gp][8kg+4+tk], q[gp+8][8kg+4+tk]}
    for (int w = tid; w < NK * 8; w += TPB) {
        const int kg = w >> 3;
        const int gp = w & 7;
        const float4* qa = reinterpret_cast<const float4*>(q + gp * DD + kg * 8);
        const float4* qb = reinterpret_cast<const float4*>(q + (gp + 8) * DD + kg * 8);
        float4 alo = qa[0], ahi = qa[1];
        float4 blo = qb[0], bhi = qb[1];
        float4* dst = qf + kg * 32 + gp * 4;
        dst[0] = make_float4(alo.x, blo.x, ahi.x, bhi.x);
        dst[1] = make_float4(alo.y, blo.y, ahi.y, bhi.y);
        dst[2] = make_float4(alo.z, blo.z, ahi.z, bhi.z);
        dst[3] = make_float4(alo.w, blo.w, ahi.w, bhi.w);
    }
    __syncthreads();   // qf visible to all warps (only block barrier)

    const int tk = lane & 3;                   // thread-in-group (k index)
    const int g  = lane >> 2;                  // group id (row / n index)

    float c[NT][4];
    #pragma unroll
    for (int nt = 0; nt < NT; ++nt)
        #pragma unroll
        for (int i = 0; i < 4; ++i) c[nt][i] = 0.f;

    for (int kg = 0; kg < NK; ++kg) {
        // issue stage kg+NSTAGE-1 (buffer consumed at kg-1; warp-private)
        if (kg + NSTAGE - 1 < NK) {
            const float* src = gsrc + (size_t)((kg + NSTAGE - 1) * 8) * NCOL;
            uint32_t dst = sbase +
                (uint32_t)((kg + NSTAGE - 1) & (NSTAGE - 1)) * (SB_TILE * 4);
            cp16(dst, src);
            cp16(dst + 16, src + 4);
        }
        asm volatile("cp.async.commit_group;" ::: "memory");
        asm volatile("cp.async.wait_group 3;" ::: "memory");   // stage kg ready
        __syncwarp();

        // A fragment: one LDS.128 (raw bits; HW truncates to tf32)
        float4 af = qf[kg * 32 + lane];
        uint32_t ah[4] = {__float_as_uint(af.x), __float_as_uint(af.y),
                          __float_as_uint(af.z), __float_as_uint(af.w)};

        const float* sb = wB + (kg & (NSTAGE - 1)) * SB_TILE;
        #pragma unroll
        for (int nt = 0; nt < NT; ++nt) {
            const int cB = nt * 8 + g;
            uint32_t b0 = __float_as_uint(sb[tk * SB_STRIDE + cB]);
            uint32_t b1 = __float_as_uint(sb[(tk + 4) * SB_STRIDE + cB]);
            mma_tf32(c[nt], ah, b0, b1);
        }
    }

    // --- epilogue: per-thread top2 for rows g and g+8, quad reduce ---
    float v1l = neg_inf(), v2l = neg_inf();
    int i1l = 0x7fffffff, i2l = 0x7fffffff;
    float v1h = neg_inf(), v2h = neg_inf();
    int i1h = 0x7fffffff, i2h = 0x7fffffff;

    #pragma unroll
    for (int nt = 0; nt < NT; ++nt) {
        const int col0 = cb + wid * WCOLS + nt * 8 + 2 * tk;
        const int col1 = col0 + 1;
        const bool ok0 = (col0 < NCOL) && !(col0 >= start && col0 < end);
        const bool ok1 = (col1 < NCOL) && !(col1 >= start && col1 < end);
        if (ok0) {
            merge_one(v1l, i1l, v2l, i2l, c[nt][0], col0);
            merge_one(v1h, i1h, v2h, i2h, c[nt][2], col0);
        }
        if (ok1) {
            merge_one(v1l, i1l, v2l, i2l, c[nt][1], col1);
            merge_one(v1h, i1h, v2h, i2h, c[nt][3], col1);
        }
    }
    #pragma unroll
    for (int off = 1; off <= 2; off <<= 1) {
        float w1, w2; int j1, j2;
        w1 = __shfl_xor_sync(0xffffffffu, v1l, off);
        j1 = __shfl_xor_sync(0xffffffffu, i1l, off);
        w2 = __shfl_xor_sync(0xffffffffu, v2l, off);
        j2 = __shfl_xor_sync(0xffffffffu, i2l, off);
        merge_pair(v1l, i1l, v2l, i2l, w1, j1, w2, j2);
        w1 = __shfl_xor_sync(0xffffffffu, v1h, off);
        j1 = __shfl_xor_sync(0xffffffffu, i1h, off);
        w2 = __shfl_xor_sync(0xffffffffu, v2h, off);
        j2 = __shfl_xor_sync(0xffffffffu, i2h, off);
        merge_pair(v1h, i1h, v2h, i2h, w1, j1, w2, j2);
    }
    if (tk == 0) {
        Top2 tl; tl.v1 = v1l; tl.v2 = v2l; tl.i1 = i1l; tl.i2 = i2l;
        sred[wid * 16 + g] = tl;
        Top2 th; th.v1 = v1h; th.v2 = v2h; th.i1 = i1h; th.i2 = i2h;
        sred[wid * 16 + 8 + g] = th;
    }
    __syncthreads();

    if (tid < QN) {
        float v1 = neg_inf(), v2 = neg_inf();
        int i1 = 0x7fffffff, i2 = 0x7fffffff;
        #pragma unroll
        for (int w = 0; w < NWARP; ++w) {
            Top2 t = sred[w * 16 + tid];
            merge_pair(v1, i1, v2, i2, t.v1, t.i1, t.v2, t.i2);
        }
        Top2 r; r.v1 = v1; r.v2 = v2; r.i1 = i1; r.i2 = i2;
        g_part[tid * NBLK + blockIdx.x] = r;
    }
    cudaTriggerProgrammaticLaunchCompletion();
}

// ---------------------------------------------------------------------------
// Pass 2 (fused, PDL): query-norm prologue runs BEFORE the grid dependency
// sync (overlapped with sim's tail); g_part scan + select + rescore after.
// Last block merges all candidates -> out.
// ---------------------------------------------------------------------------
__global__ __launch_bounds__(TPB) void cand_kernel(float* __restrict__ out,
                                                   const float* __restrict__ q,
                                                   const float* __restrict__ bank,
                                                   int nblocks) {
    __shared__ float sv[TPB * LK];
    __shared__ int   sc[TPB * LK];
    __shared__ float qn[DD];
    __shared__ float redv[8];
    __shared__ int   redc[8];
    __shared__ int   redp[8];
    __shared__ float candv[CTOP];
    __shared__ int   candc[CTOP];
    __shared__ unsigned int s_last;

    const int qi = blockIdx.x;
    const int part = blockIdx.y;
    const int tid = threadIdx.x;
    const int lane = tid & 31;
    const int warp = tid >> 5;

    const int chunk = (nblocks + NPART - 1) / NPART;
    const int b0 = part * chunk;
    const int b1 = min(nblocks, b0 + chunk);

    // --- PDL prologue: normalized query (independent of sim's output) ---
    float s = 0.f;
    for (int d = tid; d < DD; d += TPB) s += fabsf(q[qi * DD + d]);
    #pragma unroll
    for (int o = 16; o; o >>= 1) s += __shfl_xor_sync(0xffffffffu, s, o);
    if (lane == 0) redv[warp] = s;
    __syncthreads();
    if (tid == 0) {
        float tot = 0.f;
        #pragma unroll
        for (int w = 0; w < 8; ++w) tot += redv[w];
        redv[0] = 1.0f / fmaxf(tot, 1e-12f);
    }
    __syncthreads();
    const float inv = redv[0];
    for (int d = tid; d < DD; d += TPB) qn[d] = q[qi * DD + d] * inv;
    __syncthreads();

    // wait for sim_kernel's g_part writes to be visible
    cudaGridDependencySynchronize();

    // --- per-thread top-2 over coalesced partial slice ---
    float lv[LK];
    int   lc[LK];
    #pragma unroll
    for (int i = 0; i < LK; ++i) { lv[i] = neg_inf(); lc[i] = 0x7fffffff; }

    const Top2* gp = g_part + (size_t)qi * nblocks;
    for (int b = b0 + tid; b < b1; b += TPB) {
        Top2 t = gp[b];
        #pragma unroll
        for (int h = 0; h < 2; ++h) {
            float x = h ? t.v2 : t.v1;
            int  xi = h ? t.i2 : t.i1;
            if (before(x, xi, lv[1], lc[1])) {
                if (before(x, xi, lv[0], lc[0])) {
                    lv[1] = lv[0]; lc[1] = lc[0];
                    lv[0] = x; lc[0] = xi;
                } else { lv[1] = x; lc[1] = xi; }
            }
        }
    }
    #pragma unroll
    for (int i = 0; i < LK; ++i) {
        sv[tid + i * TPB] = lv[i];
        sc[tid + i * TPB] = lc[i];
    }
    __syncthreads();

    // --- extract top-4 from the 512 survivors ---
    for (int it = 0; it < CTOP; ++it) {
        float bv = neg_inf(); int bc = 0x7fffffff; int bp = -1;
        #pragma unroll
        for (int k = 0; k < LK; ++k) {
            int e = tid + k * TPB;
            float v = sv[e];
            int cc = sc[e];
            if (before(v, cc, bv, bc)) { bv = v; bc = cc; bp = e; }
        }
        #pragma unroll
        for (int o = 16; o; o >>= 1) {
            float wv = __shfl_xor_sync(0xffffffffu, bv, o);
            int wc = __shfl_xor_sync(0xffffffffu, bc, o);
            int wp = __shfl_xor_sync(0xffffffffu, bp, o);
            if (before(wv, wc, bv, bc)) { bv = wv; bc = wc; bp = wp; }
        }
        if (lane == 0) { redv[warp] = bv; redc[warp] = bc; redp[warp] = bp; }
        __syncthreads();
        if (tid == 0) {
            float fv = redv[0]; int fc = redc[0], fp = redp[0];
            #pragma unroll
            for (int w = 1; w < 8; ++w)
                if (before(redv[w], redc[w], fv, fc)) {
                    fv = redv[w]; fc = redc[w]; fp = redp[w];
                }
            candv[it] = fv; candc[it] = fc;
            if (fp >= 0) { sv[fp] = neg_inf(); sc[fp] = 0x7fffffff; }
        }
        __syncthreads();
    }

    // --- exact fp32 rescore of the 4 candidates (one warp per candidate) ---
    if (warp < CTOP) {
        const int col = candc[warp];
        float sum;
        if (col >= 0 && col < NCOL) {
            sum = 0.f;
            #pragma unroll
            for (int d = lane; d < DD; d += 32)
                sum += qn[d] * bank[(size_t)d * NCOL + col];
        } else {
            sum = neg_inf();
        }
        #pragma unroll
        for (int o = 16; o; o >>= 1) sum += __shfl_xor_sync(0xffffffffu, sum, o);
        if (lane == 0) {
            Cand cd; cd.v = sum; cd.i = col;
            g_cand[(qi * NPART + part) * CTOP + warp] = cd;
        }
    }
    __syncthreads();

    // --- completion counter: last block merges everything ---
    if (tid == 0) {
        __threadfence();
        unsigned int prev = atomicAdd(&g_ctr, 1u);
        s_last = (prev == (unsigned int)(QN * NPART - 1)) ? 1u : 0u;
    }
    __syncthreads();
    if (s_last) {
        __threadfence();
        // warp w merges queries w and w+8 (8 warps, 16 queries)
        #pragma unroll
        for (int qq = warp; qq < QN; qq += 8) {
            float v1 = neg_inf(), v2 = neg_inf();
            int i1 = 0x7fffffff, i2 = 0x7fffffff;
            if (lane < NPART * CTOP) {
                Cand cd = g_cand[qq * (NPART * CTOP) + lane];
                v1 = cd.v; i1 = cd.i;
            }
            #pragma unroll
            for (int o = 16; o; o >>= 1) {
                float w1 = __shfl_xor_sync(0xffffffffu, v1, o);
                int   j1 = __shfl_xor_sync(0xffffffffu, i1, o);
                float w2 = __shfl_xor_sync(0xffffffffu, v2, o);
                int   j2 = __shfl_xor_sync(0xffffffffu, i2, o);
                merge_pair(v1, i1, v2, i2, w1, j1, w2, j2);
            }
            if (lane == 0) {
                out[qq * 2 + 0] = v1;
                out[qq * 2 + 1] = v2;
                out[QN * 2 + qq * 2 + 0] = (float)i1;
                out[QN * 2 + qq * 2 + 1] = (float)i2;
            }
        }
        __syncthreads();
        if (tid == 0) g_ctr = 0;   // reset for next graph replay
    }
}

extern "C" void kernel_launch(void* const* d_in, const int* in_sizes, int n_in,
                              void* d_out, int out_size) {
    const float* q    = (const float*)d_in[0];
    const float* bank = (const float*)d_in[1];
    const int* startp = (n_in > 2) ? (const int*)d_in[2] : nullptr;
    const int* endp   = (n_in > 3) ? (const int*)d_in[3] : nullptr;
    float* out = (float*)d_out;

    static int smem_set = 0;
    if (!smem_set) {
        cudaFuncSetAttribute(sim_kernel,
                             cudaFuncAttributeMaxDynamicSharedMemorySize,
                             SMEM_BYTES);
        smem_set = 1;
    }

    sim_kernel<<<NBLK, TPB, SMEM_BYTES>>>(q, bank, startp, endp);

    // PDL launch: cand_kernel starts during sim's tail; it gates its g_part
    // reads on cudaGridDependencySynchronize().
    cudaLaunchConfig_t cfg = {};
    cfg.gridDim = dim3(QN, NPART);
    cfg.blockDim = dim3(TPB);
    cfg.dynamicSmemBytes = 0;
    cudaLaunchAttribute attrs[1];
    attrs[0].id = cudaLaunchAttributeProgrammaticStreamSerialization;
    attrs[0].val.programmaticStreamSerializationAllowed = 1;
    cfg.attrs = attrs;
    cfg.numAttrs = 1;
    cudaLaunchKernelEx(&cfg, cand_kernel, out, q, bank, (int)NBLK);
}